// round 16
// baseline (speedup 1.0000x reference)
#include <cuda_runtime.h>
#include <cuda_fp16.h>
#include <cstdint>

#define NN      50000
#define IN_C    128
#define HID     256
#define OUT_C   40
#define NLAYERS 4
#define NGROUPS 2
#define GC      128
#define NEDGES  600000
#define LN_EPS  1e-5f
#define SCAN_BLKS 196

// Scratch (device globals: allocation-free)
__device__ float  g_h[(size_t)NN * HID];
__device__ __half g_z[(size_t)NN * GC];
__device__ __half g_a16[(size_t)NN * HID];     // LN+ReLU'd GEMM input, fp16
__device__ __half g_wt1[HID * IN_C];
__device__ __half g_wtc[8 * GC * GC];
__device__ __half g_wt2[128 * HID];            // lin2_w padded 40->128 rows
__device__ int    g_cnt[NN];
__device__ int    g_cur[NN];
__device__ int    g_off[NN + 1];
__device__ int    g_part[SCAN_BLKS];
__device__ int2   g_csr[NEDGES];
__device__ int    g_is64;

__device__ __forceinline__ uint32_t h2_as_u32(__half2 h)
{
    return *reinterpret_cast<uint32_t*>(&h);
}

// ---------------------------------------------------------------------------
// Weight transpose: src fp32 [K][N] (batched) -> dst fp16 [N][K]
// ---------------------------------------------------------------------------
__global__ __launch_bounds__(256) void transpose_w_kernel(
    const float* __restrict__ src, __half* __restrict__ dst, int K, int N)
{
    __shared__ float tile[32][33];
    int b  = blockIdx.z;
    const float* s = src + (size_t)b * K * N;
    __half*      d = dst + (size_t)b * K * N;
    int k0 = blockIdx.y * 32, n0 = blockIdx.x * 32;
    int tx = threadIdx.x & 31, ty = threadIdx.x >> 5;
#pragma unroll
    for (int j = ty; j < 32; j += 8) {
        int k = k0 + j, n = n0 + tx;
        tile[j][tx] = (k < K && n < N) ? s[(size_t)k * N + n] : 0.f;
    }
    __syncthreads();
#pragma unroll
    for (int j = ty; j < 32; j += 8) {
        int n = n0 + j, k = k0 + tx;
        if (n < N && k < K) d[(size_t)n * K + k] = __float2half(tile[tx][j]);
    }
}

// ---------------------------------------------------------------------------
// Edge-index dtype detection (int64 vs int32)
// ---------------------------------------------------------------------------
__global__ void detect_idx_kernel(const int* __restrict__ ei32)
{
    __shared__ int nz;
    if (threadIdx.x == 0) nz = 0;
    __syncthreads();
    int bad = 0;
    for (int i = threadIdx.x; i < 2048; i += blockDim.x)
        if (ei32[2 * i + 1] != 0) bad = 1;
    if (bad) atomicOr(&nz, 1);
    __syncthreads();
    if (threadIdx.x == 0) g_is64 = (nz == 0) ? 1 : 0;
}

__device__ __forceinline__ int load_idx(const void* ei, int pos)
{
    if (g_is64) return (int)((const long long*)ei)[pos];
    return ((const int*)ei)[pos];
}

// ---------------------------------------------------------------------------
// CSR build
// ---------------------------------------------------------------------------
__global__ __launch_bounds__(256) void zero_cnt_kernel()
{
    int i = blockIdx.x * blockDim.x + threadIdx.x;
    if (i < NN) { g_cnt[i] = 0; g_cur[i] = 0; }
}

__global__ __launch_bounds__(256) void hist_kernel(const void* __restrict__ ei)
{
    int e = blockIdx.x * blockDim.x + threadIdx.x;
    if (e < NEDGES) atomicAdd(&g_cnt[load_idx(ei, NEDGES + e)], 1);
}

__global__ __launch_bounds__(256) void scan_partial_kernel()
{
    __shared__ int sm[256];
    int i = blockIdx.x * 256 + threadIdx.x;
    int v = (i < NN) ? g_cnt[i] : 0;
    sm[threadIdx.x] = v;
    __syncthreads();
#pragma unroll
    for (int o = 128; o; o >>= 1) {
        if (threadIdx.x < o) sm[threadIdx.x] += sm[threadIdx.x + o];
        __syncthreads();
    }
    if (threadIdx.x == 0) g_part[blockIdx.x] = sm[0];
}

__global__ __launch_bounds__(256) void scan_blocks_kernel()
{
    __shared__ int sm[256];
    int t = threadIdx.x;
    int v = (t < SCAN_BLKS) ? g_part[t] : 0;
    sm[t] = v;
    __syncthreads();
#pragma unroll
    for (int o = 1; o < 256; o <<= 1) {
        int u = (t >= o) ? sm[t - o] : 0;
        __syncthreads();
        sm[t] += u;
        __syncthreads();
    }
    if (t < SCAN_BLKS) g_part[t] = sm[t] - v;
}

__global__ __launch_bounds__(256) void scan_final_kernel()
{
    __shared__ int sm[256];
    int t = threadIdx.x;
    int i = blockIdx.x * 256 + t;
    int v = (i < NN) ? g_cnt[i] : 0;
    sm[t] = v;
    __syncthreads();
#pragma unroll
    for (int o = 1; o < 256; o <<= 1) {
        int u = (t >= o) ? sm[t - o] : 0;
        __syncthreads();
        sm[t] += u;
        __syncthreads();
    }
    if (i <= NN) g_off[i] = g_part[blockIdx.x] + sm[t] - v;
}

__global__ __launch_bounds__(256) void fill_kernel(
    const void* __restrict__ ei, const float* __restrict__ ew)
{
    int e = blockIdx.x * blockDim.x + threadIdx.x;
    if (e >= NEDGES) return;
    int srcv = load_idx(ei, e);
    int d    = load_idx(ei, NEDGES + e);
    int pos = g_off[d] + atomicAdd(&g_cur[d], 1);
    g_csr[pos] = make_int2(srcv, __float_as_int(ew[e]));
}

// ---------------------------------------------------------------------------
// fp16 MMA + ldmatrix helpers
// ---------------------------------------------------------------------------
__device__ __forceinline__ void mma_f16(float* c, const uint32_t* a,
                                        uint32_t b0, uint32_t b1)
{
    asm volatile(
        "mma.sync.aligned.m16n8k16.row.col.f32.f16.f16.f32 "
        "{%0,%1,%2,%3}, {%4,%5,%6,%7}, {%8,%9}, {%0,%1,%2,%3};"
        : "+f"(c[0]), "+f"(c[1]), "+f"(c[2]), "+f"(c[3])
        : "r"(a[0]), "r"(a[1]), "r"(a[2]), "r"(a[3]), "r"(b0), "r"(b1));
}

__device__ __forceinline__ void ldsm_x4(uint32_t& r0, uint32_t& r1,
                                        uint32_t& r2, uint32_t& r3,
                                        uint32_t saddr)
{
    asm volatile(
        "ldmatrix.sync.aligned.m8n8.x4.shared.b16 {%0,%1,%2,%3}, [%4];"
        : "=r"(r0), "=r"(r1), "=r"(r2), "=r"(r3) : "r"(saddr));
}

// ---------------------------------------------------------------------------
// Weight-resident persistent fp16 GEMM (fp32 accum), K = KD (128 or 256).
// HALF_IN: A already fp16. LN1EPI: blocks with colblk==128 also compute the
// first LayerNorm over their 128 output columns and write a16 (fp16).
// ---------------------------------------------------------------------------
template<bool HALF_IN, bool HALF_OUT, int KD, bool LN1EPI>
__global__ __launch_bounds__(256, KD == 128 ? 2 : 1) void gemm_f16_kernel(
    const void* __restrict__ Av, int lda,
    const __half* __restrict__ Wt,
    const float* __restrict__ bias, void* __restrict__ Cv, int ldc,
    int nrows, int ncol_lim,
    const float* __restrict__ gamma, const float* __restrict__ beta,
    __half* __restrict__ a16)
{
    constexpr int PF = KD / 2 + 4;
    constexpr int AI = KD / 8;
    constexpr int BI = KD / 16;

    extern __shared__ uint32_t smem[];
    uint32_t* Bs  = smem;
    uint32_t* As0 = smem + 128 * PF;
    uint32_t* As1 = As0 + 128 * PF;

    const int tid  = threadIdx.x;
    const int wid  = tid >> 5;
    const int lane = tid & 31;
    const int gid  = lane >> 2;
    const int tig  = lane & 3;
    const int wm   = (wid & 3) * 32;
    const int wn   = (wid >> 2) * 64;
    const int colblk = blockIdx.y * 128;
    const int NRB  = (nrows + 127) >> 7;
    const bool lnepi = LN1EPI && (colblk == 128);

    const int lrow = lane & 15;
    const int lkof = (lane >> 4) * 4;
    const uint32_t bs_base  = (uint32_t)__cvta_generic_to_shared(Bs);
    const uint32_t as0_base = (uint32_t)__cvta_generic_to_shared(As0);
    const uint32_t as1_base = (uint32_t)__cvta_generic_to_shared(As1);
    uint32_t aoff[2], boff[4];
#pragma unroll
    for (int mt = 0; mt < 2; mt++)
        aoff[mt] = ((wm + mt * 16 + lrow) * PF + lkof) * 4;
#pragma unroll
    for (int p = 0; p < 4; p++)
        boff[p] = ((wn + p * 16 + lrow) * PF + lkof) * 4;

    // resident B load
#pragma unroll
    for (int i = 0; i < BI; i++) {
        int q   = tid + i * 256;
        int n   = q / (KD / 8);
        int kh8 = (q % (KD / 8)) * 8;
        uint4 v = *(const uint4*)(Wt + (size_t)(colblk + n) * KD + kh8);
        *(uint4*)&Bs[n * PF + (kh8 >> 1)] = v;
    }

    uint32_t raf[HALF_IN ? 1 : AI][2];
    uint4    rah[HALF_IN ? BI : 1];

    auto loadA = [&](int rb) {
        int rowblk = rb * 128;
        if (HALF_IN) {
#pragma unroll
            for (int i = 0; i < BI; i++) {
                int q   = tid + i * 256;
                int r   = q / (KD / 8);
                int kh8 = (q % (KD / 8)) * 8;
                int grow = rowblk + r;
                uint4 v = make_uint4(0u, 0u, 0u, 0u);
                if (grow < nrows)
                    v = *(const uint4*)((const __half*)Av + (size_t)grow * lda + kh8);
                rah[i] = v;
            }
        } else {
#pragma unroll
            for (int i = 0; i < AI; i++) {
                int q  = tid + i * 256;
                int r  = q / (KD / 4);
                int c4 = (q % (KD / 4)) * 4;
                int grow = rowblk + r;
                float4 v = make_float4(0.f, 0.f, 0.f, 0.f);
                if (grow < nrows)
                    v = *(const float4*)((const float*)Av + (size_t)grow * lda + c4);
                raf[i][0] = h2_as_u32(__floats2half2_rn(v.x, v.y));
                raf[i][1] = h2_as_u32(__floats2half2_rn(v.z, v.w));
            }
        }
    };

    auto storeA = [&](uint32_t* As) {
        if (HALF_IN) {
#pragma unroll
            for (int i = 0; i < BI; i++) {
                int q   = tid + i * 256;
                int r   = q / (KD / 8);
                int kh8 = (q % (KD / 8)) * 8;
                *(uint4*)&As[r * PF + (kh8 >> 1)] = rah[i];
            }
        } else {
#pragma unroll
            for (int i = 0; i < AI; i++) {
                int q  = tid + i * 256;
                int r  = q / (KD / 4);
                int c4 = (q % (KD / 4)) * 4;
                *(uint2*)&As[r * PF + (c4 >> 1)] = make_uint2(raf[i][0], raf[i][1]);
            }
        }
    };

    float c[2][8][4];

    int rb = blockIdx.x;
    if (rb >= NRB) return;
    loadA(rb);
    storeA(As0);
    __syncthreads();

    int buf = 0;
    for (;;) {
        int rb_next = rb + gridDim.x;
        bool more = rb_next < NRB;
        if (more) loadA(rb_next);

#pragma unroll
        for (int mt = 0; mt < 2; mt++)
#pragma unroll
            for (int nt = 0; nt < 8; nt++)
#pragma unroll
                for (int r = 0; r < 4; r++) c[mt][nt][r] = 0.f;

        const uint32_t as_base = buf ? as1_base : as0_base;
#pragma unroll
        for (int ks = 0; ks < KD / 16; ks++) {
            const uint32_t khb = ks * 32;
            uint32_t a[2][4];
            ldsm_x4(a[0][0], a[0][1], a[0][2], a[0][3], as_base + aoff[0] + khb);
            ldsm_x4(a[1][0], a[1][1], a[1][2], a[1][3], as_base + aoff[1] + khb);
#pragma unroll
            for (int p = 0; p < 4; p++) {
                uint32_t b0A, b0B, b1A, b1B;
                ldsm_x4(b0A, b0B, b1A, b1B, bs_base + boff[p] + khb);
                mma_f16(c[0][2 * p],     a[0], b0A, b1A);
                mma_f16(c[1][2 * p],     a[1], b0A, b1A);
                mma_f16(c[0][2 * p + 1], a[0], b0B, b1B);
                mma_f16(c[1][2 * p + 1], a[1], b0B, b1B);
            }
        }

        int rowblk = rb * 128;

        // ---- LN1 epilogue (lin1 colblk==1 only) ----
        if (lnepi) {
#pragma unroll
            for (int mt = 0; mt < 2; mt++)
#pragma unroll
                for (int nt = 0; nt < 8; nt++) {
                    int col = colblk + wn + nt * 8 + 2 * tig;
                    float bx = bias[col], by = bias[col + 1];
                    c[mt][nt][0] += bx; c[mt][nt][1] += by;
                    c[mt][nt][2] += bx; c[mt][nt][3] += by;
                }
            float s[2][2], sq[2][2];
#pragma unroll
            for (int mt = 0; mt < 2; mt++)
#pragma unroll
                for (int rh = 0; rh < 2; rh++) {
                    float ts = 0.f, tq = 0.f;
#pragma unroll
                    for (int nt = 0; nt < 8; nt++) {
                        float v0 = c[mt][nt][rh * 2];
                        float v1 = c[mt][nt][rh * 2 + 1];
                        ts += v0 + v1;
                        tq += v0 * v0 + v1 * v1;
                    }
                    s[mt][rh] = ts; sq[mt][rh] = tq;
                }
#pragma unroll
            for (int o = 1; o <= 2; o <<= 1)
#pragma unroll
                for (int mt = 0; mt < 2; mt++)
#pragma unroll
                    for (int rh = 0; rh < 2; rh++) {
                        s[mt][rh]  += __shfl_xor_sync(0xffffffffu, s[mt][rh], o);
                        sq[mt][rh] += __shfl_xor_sync(0xffffffffu, sq[mt][rh], o);
                    }
            __syncthreads();
            float2* scr = (float2*)(buf ? As1 : As0);
            int wnh = wn >> 6;
            if (tig == 0) {
#pragma unroll
                for (int mt = 0; mt < 2; mt++)
#pragma unroll
                    for (int rh = 0; rh < 2; rh++) {
                        int rl = wm + mt * 16 + rh * 8 + gid;
                        scr[rl * 2 + wnh] = make_float2(s[mt][rh], sq[mt][rh]);
                    }
            }
            __syncthreads();
#pragma unroll
            for (int mt = 0; mt < 2; mt++)
#pragma unroll
                for (int rh = 0; rh < 2; rh++) {
                    int rl = wm + mt * 16 + rh * 8 + gid;
                    float2 pa = scr[rl * 2];
                    float2 pb = scr[rl * 2 + 1];
                    float S  = pa.x + pb.x;
                    float SQ = pa.y + pb.y;
                    float mu  = S * (1.f / 128.f);
                    float var = SQ * (1.f / 128.f) - mu * mu;
                    float rs  = rsqrtf(var + LN_EPS);
                    int grow = rowblk + rl;
                    if (grow < nrows) {
#pragma unroll
                        for (int nt = 0; nt < 8; nt++) {
                            int col1 = wn + nt * 8 + 2 * tig;
                            float2 g2 = *(const float2*)(gamma + col1);
                            float2 b2 = *(const float2*)(beta + col1);
                            float v0 = c[mt][nt][rh * 2];
                            float v1 = c[mt][nt][rh * 2 + 1];
                            float a0 = fmaxf((v0 - mu) * rs * g2.x + b2.x, 0.f);
                            float a1 = fmaxf((v1 - mu) * rs * g2.y + b2.y, 0.f);
                            *(__half2*)(a16 + (size_t)grow * HID + col1) =
                                __floats2half2_rn(a0, a1);
                        }
                    }
                }
        }

        // ---- common C store ----
#pragma unroll
        for (int mt = 0; mt < 2; mt++) {
            int row0 = rowblk + wm + mt * 16 + gid;
            int row1 = row0 + 8;
#pragma unroll
            for (int nt = 0; nt < 8; nt++) {
                int col = colblk + wn + nt * 8 + 2 * tig;
                if (col >= ncol_lim) continue;
                float bx = 0.f, by = 0.f;
                if (bias != nullptr && !lnepi) { bx = bias[col]; by = bias[col + 1]; }
                if (HALF_OUT) {
                    __half* C = (__half*)Cv;
                    if (row0 < nrows)
                        *(__half2*)(C + (size_t)row0 * ldc + col) =
                            __floats2half2_rn(c[mt][nt][0] + bx, c[mt][nt][1] + by);
                    if (row1 < nrows)
                        *(__half2*)(C + (size_t)row1 * ldc + col) =
                            __floats2half2_rn(c[mt][nt][2] + bx, c[mt][nt][3] + by);
                } else {
                    float* C = (float*)Cv;
                    if (row0 < nrows)
                        *(float2*)(C + (size_t)row0 * ldc + col) =
                            make_float2(c[mt][nt][0] + bx, c[mt][nt][1] + by);
                    if (row1 < nrows)
                        *(float2*)(C + (size_t)row1 * ldc + col) =
                            make_float2(c[mt][nt][2] + bx, c[mt][nt][3] + by);
                }
            }
        }

        if (!more) break;
        buf ^= 1;
        storeA(buf ? As1 : As0);
        __syncthreads();
        rb = rb_next;
    }
}

// ---------------------------------------------------------------------------
// Split-warp CSR gather: 512 threads, 8 rows/block, TWO warps per row
// (w and w+8 split the edge range; partials combined via smem). Low warp
// does h update + LN + a16 write.
// ---------------------------------------------------------------------------
__device__ __forceinline__ void acc_edge(float4& acc, const __half* z,
                                         int2 m, int lane)
{
    float w = __int_as_float(m.y);
    uint2 u = *(const uint2*)(z + (size_t)m.x * GC + lane * 4);
    float2 lo = __half22float2(*(const __half2*)&u.x);
    float2 hi = __half22float2(*(const __half2*)&u.y);
    acc.x = fmaf(w, lo.x, acc.x); acc.y = fmaf(w, lo.y, acc.y);
    acc.z = fmaf(w, hi.x, acc.z); acc.w = fmaf(w, hi.y, acc.w);
}

template<bool FULLSTATS>
__global__ __launch_bounds__(512) void gather_kernel(
    const __half* __restrict__ z, const float* __restrict__ bias,
    float* __restrict__ h, int out_ofs,
    const float* __restrict__ gnext, const float* __restrict__ bnext,
    __half* __restrict__ a16)
{
    __shared__ float4 part[8][32];

    int wid  = threadIdx.x >> 5;       // 0..15
    int lane = threadIdx.x & 31;
    int rsl  = wid & 7;                // row slot 0..7
    int half = wid >> 3;               // 0 = low, 1 = high
    int row  = blockIdx.x * 8 + rsl;
    bool valid = (row < NN);

    float4 acc = make_float4(0.f, 0.f, 0.f, 0.f);
    if (valid) {
        int s = g_off[row], e = g_off[row + 1];
        int mid = s + ((e - s + 1) >> 1);
        int lo = half ? mid : s;
        int hi = half ? e : mid;
        if (half == 0) acc = ((const float4*)bias)[lane];

        int i = lo;
        for (; i + 4 <= hi; i += 4) {
            int2 m0 = g_csr[i];
            int2 m1 = g_csr[i + 1];
            int2 m2 = g_csr[i + 2];
            int2 m3 = g_csr[i + 3];
            acc_edge(acc, z, m0, lane);
            acc_edge(acc, z, m1, lane);
            acc_edge(acc, z, m2, lane);
            acc_edge(acc, z, m3, lane);
        }
        for (; i < hi; i++)
            acc_edge(acc, z, g_csr[i], lane);
    }

    if (half == 1) part[rsl][lane] = acc;
    __syncthreads();
    if (half == 1 || !valid) return;

    float4 p = part[rsl][lane];
    acc.x += p.x; acc.y += p.y; acc.z += p.z; acc.w += p.w;

    float4* hp = (float4*)(h + (size_t)row * HID + out_ofs);
    float4 hv = hp[lane];
    hv.x += acc.x; hv.y += acc.y; hv.z += acc.z; hv.w += acc.w;
    hp[lane] = hv;

    float sm = hv.x + hv.y + hv.z + hv.w;
    float sq = hv.x * hv.x + hv.y * hv.y + hv.z * hv.z + hv.w * hv.w;
    float inv = 1.f / 128.f;
    float4 ov;
    if (FULLSTATS) {
        ov = ((const float4*)(h + (size_t)row * HID + (out_ofs ^ GC)))[lane];
        sm += ov.x + ov.y + ov.z + ov.w;
        sq += ov.x * ov.x + ov.y * ov.y + ov.z * ov.z + ov.w * ov.w;
        inv = 1.f / 256.f;
    }
#pragma unroll
    for (int o = 16; o; o >>= 1) {
        sm += __shfl_xor_sync(0xffffffffu, sm, o);
        sq += __shfl_xor_sync(0xffffffffu, sq, o);
    }
    float mu  = sm * inv;
    float var = sq * inv - mu * mu;
    float rs  = rsqrtf(var + LN_EPS);

    if (!FULLSTATS) {
        float4 g4 = ((const float4*)gnext)[lane];
        float4 b4 = ((const float4*)bnext)[lane];
        float a0 = fmaxf((hv.x - mu) * rs * g4.x + b4.x, 0.f);
        float a1 = fmaxf((hv.y - mu) * rs * g4.y + b4.y, 0.f);
        float a2 = fmaxf((hv.z - mu) * rs * g4.z + b4.z, 0.f);
        float a3 = fmaxf((hv.w - mu) * rs * g4.w + b4.w, 0.f);
        *(uint2*)(a16 + (size_t)row * HID + lane * 4) =
            make_uint2(h2_as_u32(__floats2half2_rn(a0, a1)),
                       h2_as_u32(__floats2half2_rn(a2, a3)));
    } else {
        int c_hv = out_ofs + lane * 4;
        int c_ov = (out_ofs ^ GC) + lane * 4;
        float4 g4 = *(const float4*)(gnext + c_hv);
        float4 b4 = *(const float4*)(bnext + c_hv);
        float a0 = fmaxf((hv.x - mu) * rs * g4.x + b4.x, 0.f);
        float a1 = fmaxf((hv.y - mu) * rs * g4.y + b4.y, 0.f);
        float a2 = fmaxf((hv.z - mu) * rs * g4.z + b4.z, 0.f);
        float a3 = fmaxf((hv.w - mu) * rs * g4.w + b4.w, 0.f);
        *(uint2*)(a16 + (size_t)row * HID + c_hv) =
            make_uint2(h2_as_u32(__floats2half2_rn(a0, a1)),
                       h2_as_u32(__floats2half2_rn(a2, a3)));
        g4 = *(const float4*)(gnext + c_ov);
        b4 = *(const float4*)(bnext + c_ov);
        a0 = fmaxf((ov.x - mu) * rs * g4.x + b4.x, 0.f);
        a1 = fmaxf((ov.y - mu) * rs * g4.y + b4.y, 0.f);
        a2 = fmaxf((ov.z - mu) * rs * g4.z + b4.z, 0.f);
        a3 = fmaxf((ov.w - mu) * rs * g4.w + b4.w, 0.f);
        *(uint2*)(a16 + (size_t)row * HID + c_ov) =
            make_uint2(h2_as_u32(__floats2half2_rn(a0, a1)),
                       h2_as_u32(__floats2half2_rn(a2, a3)));
    }
}

// ---------------------------------------------------------------------------
extern "C" void kernel_launch(void* const* d_in, const int* in_sizes, int n_in,
                              void* d_out, int out_size)
{
    const float* x       = (const float*)d_in[0];
    const void*  ei      = d_in[1];
    const float* ew      = (const float*)d_in[2];
    const float* lin1_w  = (const float*)d_in[3];
    const float* lin1_b  = (const float*)d_in[4];
    const float* lin2_w  = (const float*)d_in[5];
    const float* lin2_b  = (const float*)d_in[6];
    const float* norm_g  = (const float*)d_in[7];
    const float* norm_b  = (const float*)d_in[8];
    const float* conv_w  = (const float*)d_in[9];
    const float* conv_b  = (const float*)d_in[10];
    const float* fnorm_g = (const float*)d_in[11];
    const float* fnorm_b = (const float*)d_in[12];
    float*       out     = (float*)d_out;

    float  *h;
    __half *z, *a16, *wt1, *wtc, *wt2;
    cudaGetSymbolAddress((void**)&h, g_h);
    cudaGetSymbolAddress((void**)&z, g_z);
    cudaGetSymbolAddress((void**)&a16, g_a16);
    cudaGetSymbolAddress((void**)&wt1, g_wt1);
    cudaGetSymbolAddress((void**)&wtc, g_wtc);
    cudaGetSymbolAddress((void**)&wt2, g_wt2);

    const int SMEM128 = 3 * 128 * (128 / 2 + 4) * 4;   // 104448 B
    const int SMEM256 = 3 * 128 * (256 / 2 + 4) * 4;   // 202752 B

    static cudaStream_t s_csr = nullptr;
    static cudaEvent_t  ev_fork = nullptr, ev_csr = nullptr;
    if (s_csr == nullptr) {
        cudaStreamCreateWithFlags(&s_csr, cudaStreamNonBlocking);
        cudaEventCreateWithFlags(&ev_fork, cudaEventDisableTiming);
        cudaEventCreateWithFlags(&ev_csr, cudaEventDisableTiming);
        cudaFuncSetAttribute((const void*)gemm_f16_kernel<false, false, 128, true>,
                             cudaFuncAttributeMaxDynamicSharedMemorySize, SMEM128);
        cudaFuncSetAttribute((const void*)gemm_f16_kernel<true, true, 128, false>,
                             cudaFuncAttributeMaxDynamicSharedMemorySize, SMEM128);
        cudaFuncSetAttribute((const void*)gemm_f16_kernel<true, false, 256, false>,
                             cudaFuncAttributeMaxDynamicSharedMemorySize, SMEM256);
    }

    const int ROW_BLKS = NN / 8;             // 6250
    const int E_BLKS   = (NEDGES + 255) / 256;
    const int N_BLKS   = (NN + 255) / 256;

    // Side stream: conv/lin2 weight transposes + full CSR build
    cudaEventRecord(ev_fork, 0);
    cudaStreamWaitEvent(s_csr, ev_fork, 0);
    transpose_w_kernel<<<dim3(GC / 32, GC / 32, 8), 256, 0, s_csr>>>(conv_w, wtc, GC, GC);
    transpose_w_kernel<<<dim3(2, HID / 32, 1), 256, 0, s_csr>>>(lin2_w, wt2, HID, OUT_C);
    detect_idx_kernel<<<1, 256, 0, s_csr>>>((const int*)ei);
    zero_cnt_kernel<<<N_BLKS, 256, 0, s_csr>>>();
    hist_kernel<<<E_BLKS, 256, 0, s_csr>>>(ei);
    scan_partial_kernel<<<SCAN_BLKS, 256, 0, s_csr>>>();
    scan_blocks_kernel<<<1, 256, 0, s_csr>>>();
    scan_final_kernel<<<SCAN_BLKS, 256, 0, s_csr>>>();
    fill_kernel<<<E_BLKS, 256, 0, s_csr>>>(ei, ew);
    cudaEventRecord(ev_csr, s_csr);

    // Main stream: lin1 transpose, lin1 GEMM (colblk 1 fuses first LN -> a16)
    transpose_w_kernel<<<dim3(HID / 32, IN_C / 32, 1), 256>>>(lin1_w, wt1, IN_C, HID);
    gemm_f16_kernel<false, false, 128, true><<<dim3(296, 2), 256, SMEM128>>>(
        x, IN_C, wt1, lin1_b, h, HID, NN, HID, norm_g, norm_b, a16);

    // Join: gathers need the CSR (and conv GEMMs need wtc)
    cudaStreamWaitEvent(0, ev_csr, 0);

    for (int l = 0; l < NLAYERS; l++) {
        for (int g = 0; g < NGROUPS; g++) {
            int out_ofs = g * GC;
            int bidx = l * NGROUPS + g;
            bool last = (bidx == NLAYERS * NGROUPS - 1);

            gemm_f16_kernel<true, true, 128, false><<<dim3(296, 1), 256, SMEM128>>>(
                a16, HID, wtc + (size_t)bidx * GC * GC, nullptr,
                z, GC, NN, GC, nullptr, nullptr, nullptr);
            if (last)
                gather_kernel<true><<<ROW_BLKS, 512>>>(
                    z, conv_b + (size_t)bidx * GC, h, out_ofs,
                    fnorm_g, fnorm_b, a16);
            else
                gather_kernel<false><<<ROW_BLKS, 512>>>(
                    z, conv_b + (size_t)bidx * GC, h, out_ofs,
                    norm_g + (size_t)(bidx + 1) * GC,
                    norm_b + (size_t)(bidx + 1) * GC, a16);
        }
    }

    // lin2: out = a16(final LN applied) @ wt2 + b
    gemm_f16_kernel<true, false, 256, false><<<dim3(148, 1), 256, SMEM256>>>(
        a16, HID, wt2, lin2_b, out, OUT_C, NN, OUT_C, nullptr, nullptr, nullptr);
}

// round 17
// speedup vs baseline: 1.1867x; 1.1867x over previous
#include <cuda_runtime.h>
#include <cuda_fp16.h>
#include <cstdint>

#define NN      50000
#define IN_C    128
#define HID     256
#define OUT_C   40
#define NLAYERS 4
#define NGROUPS 2
#define GC      128
#define NEDGES  600000
#define LN_EPS  1e-5f
#define SCAN_BLKS 196

// Scratch (device globals: allocation-free)
__device__ float  g_h[(size_t)NN * HID];
__device__ __half g_z[(size_t)NN * GC];
__device__ __half g_a16[(size_t)NN * HID];     // LN+ReLU'd GEMM input, fp16
__device__ __half g_wt1[HID * IN_C];
__device__ __half g_wtc[8 * GC * GC];
__device__ __half g_wt2[128 * HID];            // lin2_w padded 40->128 rows
__device__ int    g_cnt[NN];
__device__ int    g_cur[NN];
__device__ int    g_off[NN + 1];
__device__ int    g_part[SCAN_BLKS];
__device__ int2   g_csr[NEDGES];
__device__ int    g_is64;

__device__ __forceinline__ uint32_t h2_as_u32(__half2 h)
{
    return *reinterpret_cast<uint32_t*>(&h);
}

// ---------------------------------------------------------------------------
// Weight transpose: src fp32 [K][N] (batched) -> dst fp16 [N][K]
// ---------------------------------------------------------------------------
__global__ __launch_bounds__(256) void transpose_w_kernel(
    const float* __restrict__ src, __half* __restrict__ dst, int K, int N)
{
    __shared__ float tile[32][33];
    int b  = blockIdx.z;
    const float* s = src + (size_t)b * K * N;
    __half*      d = dst + (size_t)b * K * N;
    int k0 = blockIdx.y * 32, n0 = blockIdx.x * 32;
    int tx = threadIdx.x & 31, ty = threadIdx.x >> 5;
#pragma unroll
    for (int j = ty; j < 32; j += 8) {
        int k = k0 + j, n = n0 + tx;
        tile[j][tx] = (k < K && n < N) ? s[(size_t)k * N + n] : 0.f;
    }
    __syncthreads();
#pragma unroll
    for (int j = ty; j < 32; j += 8) {
        int n = n0 + j, k = k0 + tx;
        if (n < N && k < K) d[(size_t)n * K + k] = __float2half(tile[tx][j]);
    }
}

// ---------------------------------------------------------------------------
// Edge-index dtype detection (int64 vs int32)
// ---------------------------------------------------------------------------
__global__ void detect_idx_kernel(const int* __restrict__ ei32)
{
    __shared__ int nz;
    if (threadIdx.x == 0) nz = 0;
    __syncthreads();
    int bad = 0;
    for (int i = threadIdx.x; i < 2048; i += blockDim.x)
        if (ei32[2 * i + 1] != 0) bad = 1;
    if (bad) atomicOr(&nz, 1);
    __syncthreads();
    if (threadIdx.x == 0) g_is64 = (nz == 0) ? 1 : 0;
}

__device__ __forceinline__ int load_idx(const void* ei, int pos)
{
    if (g_is64) return (int)((const long long*)ei)[pos];
    return ((const int*)ei)[pos];
}

// ---------------------------------------------------------------------------
// CSR build
// ---------------------------------------------------------------------------
__global__ __launch_bounds__(256) void zero_cnt_kernel()
{
    int i = blockIdx.x * blockDim.x + threadIdx.x;
    if (i < NN) { g_cnt[i] = 0; g_cur[i] = 0; }
}

__global__ __launch_bounds__(256) void hist_kernel(const void* __restrict__ ei)
{
    int e = blockIdx.x * blockDim.x + threadIdx.x;
    if (e < NEDGES) atomicAdd(&g_cnt[load_idx(ei, NEDGES + e)], 1);
}

__global__ __launch_bounds__(256) void scan_partial_kernel()
{
    __shared__ int sm[256];
    int i = blockIdx.x * 256 + threadIdx.x;
    int v = (i < NN) ? g_cnt[i] : 0;
    sm[threadIdx.x] = v;
    __syncthreads();
#pragma unroll
    for (int o = 128; o; o >>= 1) {
        if (threadIdx.x < o) sm[threadIdx.x] += sm[threadIdx.x + o];
        __syncthreads();
    }
    if (threadIdx.x == 0) g_part[blockIdx.x] = sm[0];
}

__global__ __launch_bounds__(256) void scan_blocks_kernel()
{
    __shared__ int sm[256];
    int t = threadIdx.x;
    int v = (t < SCAN_BLKS) ? g_part[t] : 0;
    sm[t] = v;
    __syncthreads();
#pragma unroll
    for (int o = 1; o < 256; o <<= 1) {
        int u = (t >= o) ? sm[t - o] : 0;
        __syncthreads();
        sm[t] += u;
        __syncthreads();
    }
    if (t < SCAN_BLKS) g_part[t] = sm[t] - v;
}

__global__ __launch_bounds__(256) void scan_final_kernel()
{
    __shared__ int sm[256];
    int t = threadIdx.x;
    int i = blockIdx.x * 256 + t;
    int v = (i < NN) ? g_cnt[i] : 0;
    sm[t] = v;
    __syncthreads();
#pragma unroll
    for (int o = 1; o < 256; o <<= 1) {
        int u = (t >= o) ? sm[t - o] : 0;
        __syncthreads();
        sm[t] += u;
        __syncthreads();
    }
    if (i <= NN) g_off[i] = g_part[blockIdx.x] + sm[t] - v;
}

__global__ __launch_bounds__(256) void fill_kernel(
    const void* __restrict__ ei, const float* __restrict__ ew)
{
    int e = blockIdx.x * blockDim.x + threadIdx.x;
    if (e >= NEDGES) return;
    int srcv = load_idx(ei, e);
    int d    = load_idx(ei, NEDGES + e);
    int pos = g_off[d] + atomicAdd(&g_cur[d], 1);
    g_csr[pos] = make_int2(srcv, __float_as_int(ew[e]));
}

// ---------------------------------------------------------------------------
// fp16 MMA + ldmatrix helpers
// ---------------------------------------------------------------------------
__device__ __forceinline__ void mma_f16(float* c, const uint32_t* a,
                                        uint32_t b0, uint32_t b1)
{
    asm volatile(
        "mma.sync.aligned.m16n8k16.row.col.f32.f16.f16.f32 "
        "{%0,%1,%2,%3}, {%4,%5,%6,%7}, {%8,%9}, {%0,%1,%2,%3};"
        : "+f"(c[0]), "+f"(c[1]), "+f"(c[2]), "+f"(c[3])
        : "r"(a[0]), "r"(a[1]), "r"(a[2]), "r"(a[3]), "r"(b0), "r"(b1));
}

__device__ __forceinline__ void ldsm_x4(uint32_t& r0, uint32_t& r1,
                                        uint32_t& r2, uint32_t& r3,
                                        uint32_t saddr)
{
    asm volatile(
        "ldmatrix.sync.aligned.m8n8.x4.shared.b16 {%0,%1,%2,%3}, [%4];"
        : "=r"(r0), "=r"(r1), "=r"(r2), "=r"(r3) : "r"(saddr));
}

// ---------------------------------------------------------------------------
// Weight-resident persistent fp16 GEMM (fp32 accum), K = KD (128 or 256).
// HALF_IN: A already fp16 (LN pre-applied by producer) -> pure uint4 copies.
// ---------------------------------------------------------------------------
template<bool HALF_IN, bool HALF_OUT, int KD>
__global__ __launch_bounds__(256, KD == 128 ? 2 : 1) void gemm_f16_kernel(
    const void* __restrict__ Av, int lda,
    const __half* __restrict__ Wt,
    const float* __restrict__ bias, void* __restrict__ Cv, int ldc,
    int nrows, int ncol_lim)
{
    constexpr int PF = KD / 2 + 4;
    constexpr int AI = KD / 8;     // fp32 chunks
    constexpr int BI = KD / 16;    // fp16 chunks

    extern __shared__ uint32_t smem[];
    uint32_t* Bs  = smem;
    uint32_t* As0 = smem + 128 * PF;
    uint32_t* As1 = As0 + 128 * PF;

    const int tid  = threadIdx.x;
    const int wid  = tid >> 5;
    const int lane = tid & 31;
    const int gid  = lane >> 2;
    const int tig  = lane & 3;
    const int wm   = (wid & 3) * 32;
    const int wn   = (wid >> 2) * 64;
    const int colblk = blockIdx.y * 128;
    const int NRB  = (nrows + 127) >> 7;

    const int lrow = lane & 15;
    const int lkof = (lane >> 4) * 4;
    const uint32_t bs_base  = (uint32_t)__cvta_generic_to_shared(Bs);
    const uint32_t as0_base = (uint32_t)__cvta_generic_to_shared(As0);
    const uint32_t as1_base = (uint32_t)__cvta_generic_to_shared(As1);
    uint32_t aoff[2], boff[4];
#pragma unroll
    for (int mt = 0; mt < 2; mt++)
        aoff[mt] = ((wm + mt * 16 + lrow) * PF + lkof) * 4;
#pragma unroll
    for (int p = 0; p < 4; p++)
        boff[p] = ((wn + p * 16 + lrow) * PF + lkof) * 4;

    // resident B load
#pragma unroll
    for (int i = 0; i < BI; i++) {
        int q   = tid + i * 256;
        int n   = q / (KD / 8);
        int kh8 = (q % (KD / 8)) * 8;
        uint4 v = *(const uint4*)(Wt + (size_t)(colblk + n) * KD + kh8);
        *(uint4*)&Bs[n * PF + (kh8 >> 1)] = v;
    }

    uint32_t raf[HALF_IN ? 1 : AI][2];   // fp32 staging
    uint4    rah[HALF_IN ? BI : 1];      // fp16 staging

    auto loadA = [&](int rb) {
        int rowblk = rb * 128;
        if (HALF_IN) {
#pragma unroll
            for (int i = 0; i < BI; i++) {
                int q   = tid + i * 256;
                int r   = q / (KD / 8);
                int kh8 = (q % (KD / 8)) * 8;
                int grow = rowblk + r;
                uint4 v = make_uint4(0u, 0u, 0u, 0u);
                if (grow < nrows)
                    v = *(const uint4*)((const __half*)Av + (size_t)grow * lda + kh8);
                rah[i] = v;
            }
        } else {
#pragma unroll
            for (int i = 0; i < AI; i++) {
                int q  = tid + i * 256;
                int r  = q / (KD / 4);
                int c4 = (q % (KD / 4)) * 4;
                int grow = rowblk + r;
                float4 v = make_float4(0.f, 0.f, 0.f, 0.f);
                if (grow < nrows)
                    v = *(const float4*)((const float*)Av + (size_t)grow * lda + c4);
                raf[i][0] = h2_as_u32(__floats2half2_rn(v.x, v.y));
                raf[i][1] = h2_as_u32(__floats2half2_rn(v.z, v.w));
            }
        }
    };

    auto storeA = [&](uint32_t* As) {
        if (HALF_IN) {
#pragma unroll
            for (int i = 0; i < BI; i++) {
                int q   = tid + i * 256;
                int r   = q / (KD / 8);
                int kh8 = (q % (KD / 8)) * 8;
                *(uint4*)&As[r * PF + (kh8 >> 1)] = rah[i];
            }
        } else {
#pragma unroll
            for (int i = 0; i < AI; i++) {
                int q  = tid + i * 256;
                int r  = q / (KD / 4);
                int c4 = (q % (KD / 4)) * 4;
                *(uint2*)&As[r * PF + (c4 >> 1)] = make_uint2(raf[i][0], raf[i][1]);
            }
        }
    };

    float c[2][8][4];

    int rb = blockIdx.x;
    if (rb >= NRB) return;
    loadA(rb);
    storeA(As0);
    __syncthreads();

    int buf = 0;
    for (;;) {
        int rb_next = rb + gridDim.x;
        bool more = rb_next < NRB;
        if (more) loadA(rb_next);

#pragma unroll
        for (int mt = 0; mt < 2; mt++)
#pragma unroll
            for (int nt = 0; nt < 8; nt++)
#pragma unroll
                for (int r = 0; r < 4; r++) c[mt][nt][r] = 0.f;

        const uint32_t as_base = buf ? as1_base : as0_base;
#pragma unroll
        for (int ks = 0; ks < KD / 16; ks++) {
            const uint32_t khb = ks * 32;
            uint32_t a[2][4];
            ldsm_x4(a[0][0], a[0][1], a[0][2], a[0][3], as_base + aoff[0] + khb);
            ldsm_x4(a[1][0], a[1][1], a[1][2], a[1][3], as_base + aoff[1] + khb);
#pragma unroll
            for (int p = 0; p < 4; p++) {
                uint32_t b0A, b0B, b1A, b1B;
                ldsm_x4(b0A, b0B, b1A, b1B, bs_base + boff[p] + khb);
                mma_f16(c[0][2 * p],     a[0], b0A, b1A);
                mma_f16(c[1][2 * p],     a[1], b0A, b1A);
                mma_f16(c[0][2 * p + 1], a[0], b0B, b1B);
                mma_f16(c[1][2 * p + 1], a[1], b0B, b1B);
            }
        }

        int rowblk = rb * 128;
#pragma unroll
        for (int mt = 0; mt < 2; mt++) {
            int row0 = rowblk + wm + mt * 16 + gid;
            int row1 = row0 + 8;
#pragma unroll
            for (int nt = 0; nt < 8; nt++) {
                int col = colblk + wn + nt * 8 + 2 * tig;
                if (col >= ncol_lim) continue;
                float bx = 0.f, by = 0.f;
                if (bias != nullptr) { bx = bias[col]; by = bias[col + 1]; }
                if (HALF_OUT) {
                    __half* C = (__half*)Cv;
                    if (row0 < nrows)
                        *(__half2*)(C + (size_t)row0 * ldc + col) =
                            __floats2half2_rn(c[mt][nt][0] + bx, c[mt][nt][1] + by);
                    if (row1 < nrows)
                        *(__half2*)(C + (size_t)row1 * ldc + col) =
                            __floats2half2_rn(c[mt][nt][2] + bx, c[mt][nt][3] + by);
                } else {
                    float* C = (float*)Cv;
                    if (row0 < nrows)
                        *(float2*)(C + (size_t)row0 * ldc + col) =
                            make_float2(c[mt][nt][0] + bx, c[mt][nt][1] + by);
                    if (row1 < nrows)
                        *(float2*)(C + (size_t)row1 * ldc + col) =
                            make_float2(c[mt][nt][2] + bx, c[mt][nt][3] + by);
                }
            }
        }

        if (!more) break;
        buf ^= 1;
        storeA(buf ? As1 : As0);
        __syncthreads();
        rb = rb_next;
    }
}

// ---------------------------------------------------------------------------
// LN+ReLU apply after lin1: stats over h[:,128:256], writes a16[:,0:128] fp16
// with block-0 gamma/beta. One warp per row.
// ---------------------------------------------------------------------------
__global__ __launch_bounds__(256) void ln_apply_kernel(
    const float* __restrict__ h,
    const float* __restrict__ gamma, const float* __restrict__ beta,
    __half* __restrict__ a16)
{
    int row = blockIdx.x * 8 + (threadIdx.x >> 5);
    int lane = threadIdx.x & 31;
    if (row >= NN) return;
    float4 v = ((const float4*)(h + (size_t)row * HID + GC))[lane];
    float s  = v.x + v.y + v.z + v.w;
    float sq = v.x * v.x + v.y * v.y + v.z * v.z + v.w * v.w;
#pragma unroll
    for (int o = 16; o; o >>= 1) {
        s  += __shfl_xor_sync(0xffffffffu, s, o);
        sq += __shfl_xor_sync(0xffffffffu, sq, o);
    }
    float mu  = s * (1.f / 128.f);
    float var = sq * (1.f / 128.f) - mu * mu;
    float rs  = rsqrtf(var + LN_EPS);

    float4 g4 = ((const float4*)gamma)[lane];
    float4 b4 = ((const float4*)beta)[lane];
    float a0 = fmaxf((v.x - mu) * rs * g4.x + b4.x, 0.f);
    float a1 = fmaxf((v.y - mu) * rs * g4.y + b4.y, 0.f);
    float a2 = fmaxf((v.z - mu) * rs * g4.z + b4.z, 0.f);
    float a3 = fmaxf((v.w - mu) * rs * g4.w + b4.w, 0.f);
    *(uint2*)(a16 + (size_t)row * HID + lane * 4) =
        make_uint2(h2_as_u32(__floats2half2_rn(a0, a1)),
                   h2_as_u32(__floats2half2_rn(a2, a3)));
}

// ---------------------------------------------------------------------------
// CSR gather + bias + in-place h update + next LN+ReLU -> a16.
// One warp per row; edge loop unrolled x8 for deeper MLP.
// ---------------------------------------------------------------------------
__device__ __forceinline__ void acc_edge(float4& acc, const __half* z,
                                         int2 m, int lane)
{
    float w = __int_as_float(m.y);
    uint2 u = *(const uint2*)(z + (size_t)m.x * GC + lane * 4);
    float2 lo = __half22float2(*(const __half2*)&u.x);
    float2 hi = __half22float2(*(const __half2*)&u.y);
    acc.x = fmaf(w, lo.x, acc.x); acc.y = fmaf(w, lo.y, acc.y);
    acc.z = fmaf(w, hi.x, acc.z); acc.w = fmaf(w, hi.y, acc.w);
}

template<bool FULLSTATS>
__global__ __launch_bounds__(256) void gather_kernel(
    const __half* __restrict__ z, const float* __restrict__ bias,
    float* __restrict__ h, int out_ofs,
    const float* __restrict__ gnext, const float* __restrict__ bnext,
    __half* __restrict__ a16)
{
    int row = blockIdx.x * 8 + (threadIdx.x >> 5);
    int lane = threadIdx.x & 31;
    if (row >= NN) return;

    float4 acc = ((const float4*)bias)[lane];
    int s = g_off[row], e = g_off[row + 1];

    int i = s;
    for (; i + 8 <= e; i += 8) {
        int2 m0 = g_csr[i];
        int2 m1 = g_csr[i + 1];
        int2 m2 = g_csr[i + 2];
        int2 m3 = g_csr[i + 3];
        int2 m4 = g_csr[i + 4];
        int2 m5 = g_csr[i + 5];
        int2 m6 = g_csr[i + 6];
        int2 m7 = g_csr[i + 7];
        acc_edge(acc, z, m0, lane);
        acc_edge(acc, z, m1, lane);
        acc_edge(acc, z, m2, lane);
        acc_edge(acc, z, m3, lane);
        acc_edge(acc, z, m4, lane);
        acc_edge(acc, z, m5, lane);
        acc_edge(acc, z, m6, lane);
        acc_edge(acc, z, m7, lane);
    }
    if (i + 4 <= e) {
        int2 m0 = g_csr[i];
        int2 m1 = g_csr[i + 1];
        int2 m2 = g_csr[i + 2];
        int2 m3 = g_csr[i + 3];
        acc_edge(acc, z, m0, lane);
        acc_edge(acc, z, m1, lane);
        acc_edge(acc, z, m2, lane);
        acc_edge(acc, z, m3, lane);
        i += 4;
    }
    for (; i < e; i++)
        acc_edge(acc, z, g_csr[i], lane);

    float4* hp = (float4*)(h + (size_t)row * HID + out_ofs);
    float4 hv = hp[lane];
    hv.x += acc.x; hv.y += acc.y; hv.z += acc.z; hv.w += acc.w;
    hp[lane] = hv;

    float sm = hv.x + hv.y + hv.z + hv.w;
    float sq = hv.x * hv.x + hv.y * hv.y + hv.z * hv.z + hv.w * hv.w;
    float inv = 1.f / 128.f;
    float4 ov;
    if (FULLSTATS) {
        ov = ((const float4*)(h + (size_t)row * HID + (out_ofs ^ GC)))[lane];
        sm += ov.x + ov.y + ov.z + ov.w;
        sq += ov.x * ov.x + ov.y * ov.y + ov.z * ov.z + ov.w * ov.w;
        inv = 1.f / 256.f;
    }
#pragma unroll
    for (int o = 16; o; o >>= 1) {
        sm += __shfl_xor_sync(0xffffffffu, sm, o);
        sq += __shfl_xor_sync(0xffffffffu, sq, o);
    }
    float mu  = sm * inv;
    float var = sq * inv - mu * mu;
    float rs  = rsqrtf(var + LN_EPS);

    if (!FULLSTATS) {
        float4 g4 = ((const float4*)gnext)[lane];
        float4 b4 = ((const float4*)bnext)[lane];
        float a0 = fmaxf((hv.x - mu) * rs * g4.x + b4.x, 0.f);
        float a1 = fmaxf((hv.y - mu) * rs * g4.y + b4.y, 0.f);
        float a2 = fmaxf((hv.z - mu) * rs * g4.z + b4.z, 0.f);
        float a3 = fmaxf((hv.w - mu) * rs * g4.w + b4.w, 0.f);
        *(uint2*)(a16 + (size_t)row * HID + lane * 4) =
            make_uint2(h2_as_u32(__floats2half2_rn(a0, a1)),
                       h2_as_u32(__floats2half2_rn(a2, a3)));
    } else {
        int c_hv = out_ofs + lane * 4;
        int c_ov = (out_ofs ^ GC) + lane * 4;
        float4 g4 = *(const float4*)(gnext + c_hv);
        float4 b4 = *(const float4*)(bnext + c_hv);
        float a0 = fmaxf((hv.x - mu) * rs * g4.x + b4.x, 0.f);
        float a1 = fmaxf((hv.y - mu) * rs * g4.y + b4.y, 0.f);
        float a2 = fmaxf((hv.z - mu) * rs * g4.z + b4.z, 0.f);
        float a3 = fmaxf((hv.w - mu) * rs * g4.w + b4.w, 0.f);
        *(uint2*)(a16 + (size_t)row * HID + c_hv) =
            make_uint2(h2_as_u32(__floats2half2_rn(a0, a1)),
                       h2_as_u32(__floats2half2_rn(a2, a3)));
        g4 = *(const float4*)(gnext + c_ov);
        b4 = *(const float4*)(bnext + c_ov);
        a0 = fmaxf((ov.x - mu) * rs * g4.x + b4.x, 0.f);
        a1 = fmaxf((ov.y - mu) * rs * g4.y + b4.y, 0.f);
        a2 = fmaxf((ov.z - mu) * rs * g4.z + b4.z, 0.f);
        a3 = fmaxf((ov.w - mu) * rs * g4.w + b4.w, 0.f);
        *(uint2*)(a16 + (size_t)row * HID + c_ov) =
            make_uint2(h2_as_u32(__floats2half2_rn(a0, a1)),
                       h2_as_u32(__floats2half2_rn(a2, a3)));
    }
}

// ---------------------------------------------------------------------------
extern "C" void kernel_launch(void* const* d_in, const int* in_sizes, int n_in,
                              void* d_out, int out_size)
{
    const float* x       = (const float*)d_in[0];
    const void*  ei      = d_in[1];
    const float* ew      = (const float*)d_in[2];
    const float* lin1_w  = (const float*)d_in[3];
    const float* lin1_b  = (const float*)d_in[4];
    const float* lin2_w  = (const float*)d_in[5];
    const float* lin2_b  = (const float*)d_in[6];
    const float* norm_g  = (const float*)d_in[7];
    const float* norm_b  = (const float*)d_in[8];
    const float* conv_w  = (const float*)d_in[9];
    const float* conv_b  = (const float*)d_in[10];
    const float* fnorm_g = (const float*)d_in[11];
    const float* fnorm_b = (const float*)d_in[12];
    float*       out     = (float*)d_out;

    float  *h;
    __half *z, *a16, *wt1, *wtc, *wt2;
    cudaGetSymbolAddress((void**)&h, g_h);
    cudaGetSymbolAddress((void**)&z, g_z);
    cudaGetSymbolAddress((void**)&a16, g_a16);
    cudaGetSymbolAddress((void**)&wt1, g_wt1);
    cudaGetSymbolAddress((void**)&wtc, g_wtc);
    cudaGetSymbolAddress((void**)&wt2, g_wt2);

    const int SMEM128 = 3 * 128 * (128 / 2 + 4) * 4;   // 104448 B
    const int SMEM256 = 3 * 128 * (256 / 2 + 4) * 4;   // 202752 B

    static cudaStream_t s_csr = nullptr;
    static cudaEvent_t  ev_fork = nullptr, ev_csr = nullptr;
    if (s_csr == nullptr) {
        cudaStreamCreateWithFlags(&s_csr, cudaStreamNonBlocking);
        cudaEventCreateWithFlags(&ev_fork, cudaEventDisableTiming);
        cudaEventCreateWithFlags(&ev_csr, cudaEventDisableTiming);
        cudaFuncSetAttribute((const void*)gemm_f16_kernel<false, false, 128>,
                             cudaFuncAttributeMaxDynamicSharedMemorySize, SMEM128);
        cudaFuncSetAttribute((const void*)gemm_f16_kernel<true, true, 128>,
                             cudaFuncAttributeMaxDynamicSharedMemorySize, SMEM128);
        cudaFuncSetAttribute((const void*)gemm_f16_kernel<true, false, 256>,
                             cudaFuncAttributeMaxDynamicSharedMemorySize, SMEM256);
    }

    const int ROW_BLKS = NN / 8;             // 6250
    const int E_BLKS   = (NEDGES + 255) / 256;
    const int N_BLKS   = (NN + 255) / 256;

    // Fork CSR build (incl. dtype detect) entirely onto the side stream
    cudaEventRecord(ev_fork, 0);
    cudaStreamWaitEvent(s_csr, ev_fork, 0);
    detect_idx_kernel<<<1, 256, 0, s_csr>>>((const int*)ei);
    zero_cnt_kernel<<<N_BLKS, 256, 0, s_csr>>>();
    hist_kernel<<<E_BLKS, 256, 0, s_csr>>>(ei);
    scan_partial_kernel<<<SCAN_BLKS, 256, 0, s_csr>>>();
    scan_blocks_kernel<<<1, 256, 0, s_csr>>>();
    scan_final_kernel<<<SCAN_BLKS, 256, 0, s_csr>>>();
    fill_kernel<<<E_BLKS, 256, 0, s_csr>>>(ei, ew);
    cudaEventRecord(ev_csr, s_csr);

    // Main stream: weight transposes, lin1, first LN apply
    transpose_w_kernel<<<dim3(HID / 32, IN_C / 32, 1), 256>>>(lin1_w, wt1, IN_C, HID);
    transpose_w_kernel<<<dim3(GC / 32, GC / 32, 8), 256>>>(conv_w, wtc, GC, GC);
    transpose_w_kernel<<<dim3(2, HID / 32, 1), 256>>>(lin2_w, wt2, HID, OUT_C);

    gemm_f16_kernel<false, false, 128><<<dim3(296, 2), 256, SMEM128>>>(
        x, IN_C, wt1, lin1_b, h, HID, NN, HID);
    ln_apply_kernel<<<ROW_BLKS, 256>>>(h, norm_g, norm_b, a16);

    // Join: gathers need the CSR
    cudaStreamWaitEvent(0, ev_csr, 0);

    for (int l = 0; l < NLAYERS; l++) {
        for (int g = 0; g < NGROUPS; g++) {
            int out_ofs = g * GC;
            int bidx = l * NGROUPS + g;
            bool last = (bidx == NLAYERS * NGROUPS - 1);

            // z(fp16) = a16 @ conv_w   (a16 already LN+ReLU'd)
            gemm_f16_kernel<true, true, 128><<<dim3(296, 1), 256, SMEM128>>>(
                a16, HID, wtc + (size_t)bidx * GC * GC, nullptr,
                z, GC, NN, GC);
            if (last)
                gather_kernel<true><<<ROW_BLKS, 256>>>(
                    z, conv_b + (size_t)bidx * GC, h, out_ofs,
                    fnorm_g, fnorm_b, a16);
            else
                gather_kernel<false><<<ROW_BLKS, 256>>>(
                    z, conv_b + (size_t)bidx * GC, h, out_ofs,
                    norm_g + (size_t)(bidx + 1) * GC,
                    norm_b + (size_t)(bidx + 1) * GC, a16);
        }
    }

    // lin2: out = a16(final LN applied) @ wt2 + b
    gemm_f16_kernel<true, false, 256><<<dim3(148, 1), 256, SMEM256>>>(
        a16, HID, wt2, lin2_b, out, OUT_C, NN, OUT_C);
}